// round 15
// baseline (speedup 1.0000x reference)
#include <cuda_runtime.h>
#include <cuda_fp16.h>
#include <cstdint>
#include <cfloat>

#define CC 256
#define EE 32
#define KK 8192
#define NN 32768
#define HWW 4096
#define NT2 128          // tiles of 64 codes
#define KSPLIT 96        // split-K: [zh|zl|zh] . [eh|eh|el]
#define NKS 6            // KSPLIT/16 k-steps

#define DECAY 0.99f
#define ONE_MINUS_DECAY 0.01f
#define EPSI 1e-5f
#define BETA 0.25f

#define OFF_ZQ   0
#define OFF_IDX  1048576
#define OFF_QL   1081344
#define OFF_EMB  1081345
#define OFF_CS   1343489
#define OFF_W    1351681

// Scratch (device globals)
__device__ float g_z[NN * EE];                      // fp32 z_flat
__device__ __align__(16) __half g_bh[KK * KSPLIT];  // 1.5MB: per code row, 96 f16 = [eh|eh|el]
__device__ float g_inorm[KK];
__device__ float g_counts[KK];
__device__ float g_dw[KK * EE];
__device__ int   g_bidx[NN];
__device__ float g_qsum;
__device__ float g_nsum;

// ---------------- helpers ----------------
__device__ __forceinline__ uint32_t smem_u32(const void* p) {
    uint32_t a;
    asm("{ .reg .u64 t; cvta.to.shared.u64 t, %1; cvt.u32.u64 %0, t; }" : "=r"(a) : "l"(p));
    return a;
}
__device__ __forceinline__ void cp_async16(uint32_t saddr, const void* gaddr) {
    asm volatile("cp.async.cg.shared.global [%0], [%1], 16;" :: "r"(saddr), "l"(gaddr) : "memory");
}
__device__ __forceinline__ void mma16816(float* c, const uint32_t* a, const uint32_t* b) {
    asm volatile("mma.sync.aligned.m16n8k16.row.col.f32.f16.f16.f32 "
        "{%0,%1,%2,%3}, {%4,%5,%6,%7}, {%8,%9}, {%0,%1,%2,%3};"
        : "+f"(c[0]), "+f"(c[1]), "+f"(c[2]), "+f"(c[3])
        : "r"(a[0]), "r"(a[1]), "r"(a[2]), "r"(a[3]), "r"(b[0]), "r"(b[1]));
}
__device__ __forceinline__ void ldsm4(uint32_t* r, uint32_t addr) {
    asm volatile("ldmatrix.sync.aligned.m8n8.x4.shared.b16 {%0,%1,%2,%3}, [%4];"
        : "=r"(r[0]), "=r"(r[1]), "=r"(r[2]), "=r"(r[3]) : "r"(addr));
}
__device__ __forceinline__ void ldsm2(uint32_t* r, uint32_t addr) {
    asm volatile("ldmatrix.sync.aligned.m8n8.x2.shared.b16 {%0,%1}, [%2];"
        : "=r"(r[0]), "=r"(r[1]) : "r"(addr));
}
// XOR swizzle: rows of 256B, permute 16B chunks within each 128B half by row&7
__device__ __forceinline__ int swz(int row, int byte_) {
    int c8 = byte_ >> 4;
    int c8s = (c8 & 8) | ((c8 ^ row) & 7);
    return row * 256 + (c8s << 4) + (byte_ & 15);
}

// ---------------- zero ----------------
__global__ void zero_kernel() {
    int i = blockIdx.x * blockDim.x + threadIdx.x;
    int stride = gridDim.x * blockDim.x;
    for (int j = i; j < KK * EE; j += stride) g_dw[j] = 0.0f;
    for (int j = i; j < KK; j += stride) g_counts[j] = 0.0f;
    if (i == 0) { g_qsum = 0.0f; g_nsum = 0.0f; }
}

// ---------------- 1x1 conv ----------------
__global__ __launch_bounds__(256) void proj_kernel(
    const float* __restrict__ x, const float* __restrict__ Wq, const float* __restrict__ bq)
{
    __shared__ float sW[EE * CC];
    __shared__ float sx[CC * 16];
    const int t = threadIdx.x;
    const int n0 = blockIdx.x * 16;
    const int b = n0 >> 12;
    const int p0 = n0 & (HWW - 1);

    for (int i = t; i < EE * CC; i += 256) sW[i] = Wq[i];
    const float* xb = x + (size_t)b * CC * HWW + p0;
    #pragma unroll
    for (int j = 0; j < 16; j++) {
        int idx = j * 256 + t;
        int c = idx >> 4, pix = idx & 15;
        sx[idx] = xb[c * HWW + pix];
    }
    __syncthreads();

    const int pix = t & 15;
    const int e0 = (t >> 4) << 1;
    float a0 = 0.0f, a1 = 0.0f;
    #pragma unroll 8
    for (int c = 0; c < CC; c++) {
        float xv = sx[c * 16 + pix];
        a0 = fmaf(xv, sW[(e0 + 0) * CC + c], a0);
        a1 = fmaf(xv, sW[(e0 + 1) * CC + c], a1);
    }
    float* zr = g_z + (size_t)(n0 + pix) * EE + e0;
    zr[0] = a0 + bq[e0];
    zr[1] = a1 + bq[e0 + 1];
}

// ---------------- embedding inverse norms (scaled by 256) ----------------
__global__ __launch_bounds__(256) void inorm_kernel(const float* __restrict__ emb) {
    int k = blockIdx.x * 8 + (threadIdx.x >> 5);
    int e = threadIdx.x & 31;
    float v = emb[k * EE + e];
    float s = v * v;
    #pragma unroll
    for (int o = 16; o; o >>= 1) s += __shfl_xor_sync(0xFFFFFFFFu, s, o);
    if (e == 0) g_inorm[k] = 256.0f / fmaxf(sqrtf(s), 1e-12f);
}

// ---------------- pack B: row-major [code][96] = [eh|eh|el] ----------------
__global__ __launch_bounds__(256) void pack_bh_kernel(const float* __restrict__ emb) {
    const int code = blockIdx.x * 16 + (threadIdx.x >> 4);
    const int e0 = (threadIdx.x & 15) * 2;
    const float inv = g_inorm[code];
    float v0 = emb[(size_t)code * EE + e0] * inv;
    float v1 = emb[(size_t)code * EE + e0 + 1] * inv;
    __half h0 = __float2half_rn(v0), h1 = __float2half_rn(v1);
    __half l0 = __float2half_rn(v0 - __half2float(h0));
    __half l1 = __float2half_rn(v1 - __half2float(h1));
    __half2 hh = __halves2half2(h0, h1);
    __half2 ll = __halves2half2(l0, l1);
    __half2* row = (__half2*)(g_bh + (size_t)code * KSPLIT);
    const int i2 = e0 >> 1;
    row[i2]      = hh;   // k in [0,32)
    row[i2 + 16] = hh;   // k in [32,64)
    row[i2 + 32] = ll;   // k in [64,96)
}

// ---------------- HMMA argmax: K=96 split, A-in-regs, register argmax + cross-warp merge ----------------
// 256 CTAs x 256 thr (8 warps, 4m x 2n). M=128 pixels/CTA, 128 tiles of 64 codes.
// SMEM: A build 32KB @0 (reused: merge buffer), B double buffer 2x16KB @32768 (192B used/row).
#define SM_B_OFF 32768
#define SMEM_TOTAL (SM_B_OFF + 32768)
#define B_TILE_GBYTES (64 * KSPLIT * 2)   // 12288 B per gmem tile

__global__ __launch_bounds__(256, 2) void argmax_hmma_kernel() {
    extern __shared__ __align__(16) char smem[];
    char* smA = smem;
    const int t = threadIdx.x;
    const int l = t & 31, wid = t >> 5;
    const int wm = wid & 3, wn = wid >> 2;
    const int blk = blockIdx.x;
    const uint32_t sbA = smem_u32(smA);
    const uint32_t sbB = sbA + SM_B_OFF;

    // ---- build A tile in smem: pixel rows, K=96 = [zh|zl|zh], swizzled, 256B row stride ----
    {
        const int row = t >> 1;
        const int e0 = (t & 1) * 16;
        const float4* zr = (const float4*)(g_z + (size_t)(blk * 128 + row) * EE + e0);
        float zf[16];
        #pragma unroll
        for (int i = 0; i < 4; i++) {
            float4 v = zr[i];
            zf[4 * i] = v.x; zf[4 * i + 1] = v.y; zf[4 * i + 2] = v.z; zf[4 * i + 3] = v.w;
        }
        #pragma unroll
        for (int i = 0; i < 16; i += 2) {
            float v0 = 256.0f * zf[i];
            float v1 = 256.0f * zf[i + 1];
            __half h0 = __float2half_rn(v0), h1 = __float2half_rn(v1);
            __half l0 = __float2half_rn(v0 - __half2float(h0));
            __half l1 = __float2half_rn(v1 - __half2float(h1));
            __half2 hh = __halves2half2(h0, h1);
            __half2 ll = __halves2half2(l0, l1);
            const int b0 = 2 * (e0 + i);
            *(__half2*)(smA + swz(row, b0))       = hh;   // k = e      (zh)
            *(__half2*)(smA + swz(row, b0 + 64))  = ll;   // k = e+32   (zl)
            *(__half2*)(smA + swz(row, b0 + 128)) = hh;   // k = e+64   (zh)
        }
    }

    // ---- prologue: async-load B tile 0 (12KB packed -> padded swizzled rows) ----
    {
        const char* src = (const char*)g_bh;
        const int row = t >> 2;
        const int c3 = (t & 3) * 3;
        #pragma unroll
        for (int q = 0; q < 3; q++) {
            int c12 = c3 + q;
            int c8s = (c12 & 8) | ((c12 ^ row) & 7);
            cp_async16(sbB + row * 256 + (c8s << 4), src + row * 192 + c12 * 16);
        }
        asm volatile("cp.async.commit_group;" ::: "memory");
    }

    __syncthreads();   // A build complete

    // ---- load A fragments into registers (once), 6 k-steps ----
    const int arow0 = wm * 32 + (l & 15);
    const int abyte_lane = ((l >> 4) & 1) * 16;
    uint32_t afrag[NKS][8];   // [k-step][a0:0..3, a1:4..7]
    #pragma unroll
    for (int s = 0; s < NKS; s++) {
        const int abyte = s * 32 + abyte_lane;
        ldsm4(&afrag[s][0], sbA + swz(arow0, abyte));
        ldsm4(&afrag[s][4], sbA + swz(arow0 + 16, abyte));
    }

    // per-thread running argmax over this warp's half-columns
    float best[4] = {-FLT_MAX, -FLT_MAX, -FLT_MAX, -FLT_MAX};
    int bidx[4] = {0, 0, 0, 0};

    const int brow_lane = (l & 7);
    const int bbyte_lane = ((l >> 3) & 1) * 16;

    for (int tt = 0; tt < NT2; tt++) {
        // prefetch tile tt+1 into the other buffer
        if (tt + 1 < NT2) {
            const char* src = (const char*)g_bh + (size_t)(tt + 1) * B_TILE_GBYTES;
            uint32_t dst = sbB + ((tt + 1) & 1) * 16384;
            const int row = t >> 2;
            const int c3 = (t & 3) * 3;
            #pragma unroll
            for (int q = 0; q < 3; q++) {
                int c12 = c3 + q;
                int c8s = (c12 & 8) | ((c12 ^ row) & 7);
                cp_async16(dst + row * 256 + (c8s << 4), src + row * 192 + c12 * 16);
            }
        }
        asm volatile("cp.async.commit_group;" ::: "memory");
        asm volatile("cp.async.wait_group 1;" ::: "memory");   // B(tt) complete
        __syncthreads();   // B(tt) visible to all warps

        const uint32_t sB = sbB + (tt & 1) * 16384;

        // ---- compute 128x64 scores (6 k-steps) ----
        float c_[2][4][4];
        #pragma unroll
        for (int mi = 0; mi < 2; mi++)
            #pragma unroll
            for (int j = 0; j < 4; j++)
                #pragma unroll
                for (int q = 0; q < 4; q++) c_[mi][j][q] = 0.0f;

        #pragma unroll
        for (int s = 0; s < NKS; s++) {
            #pragma unroll
            for (int j = 0; j < 4; j++) {
                uint32_t b[2];
                const int brow = (wn * 4 + j) * 8 + brow_lane;
                ldsm2(b, sB + swz(brow, s * 32 + bbyte_lane));
                mma16816(c_[0][j], &afrag[s][0], b);
                mma16816(c_[1][j], &afrag[s][4], b);
            }
        }

        // ---- register argmax (ascending column order, strict >, explicit indices) ----
        const int colbase = tt * 64 + wn * 32 + (l & 3) * 2;
        #pragma unroll
        for (int mi = 0; mi < 2; mi++) {
            const int s0 = mi * 2;
            #pragma unroll
            for (int j = 0; j < 4; j++) {
                const int c0 = colbase + j * 8;
                if (c_[mi][j][0] > best[s0])     { best[s0] = c_[mi][j][0];     bidx[s0] = c0; }
                if (c_[mi][j][1] > best[s0])     { best[s0] = c_[mi][j][1];     bidx[s0] = c0 + 1; }
                if (c_[mi][j][2] > best[s0 + 1]) { best[s0 + 1] = c_[mi][j][2]; bidx[s0 + 1] = c0; }
                if (c_[mi][j][3] > best[s0 + 1]) { best[s0 + 1] = c_[mi][j][3]; bidx[s0 + 1] = c0 + 1; }
            }
        }
        __syncthreads();   // all warps done reading B(tt) before overwrite (tt+2)
    }

    // ---- quad reduce within warp, then cross-wn merge via smem (the R14 fix) ----
    float* mbest = (float*)smA;              // [2][128]
    int*   midx  = (int*)(smA + 1024);       // [2][128]
    #pragma unroll
    for (int slot = 0; slot < 4; slot++) {
        float v = best[slot];
        int i = bidx[slot];
        #pragma unroll
        for (int o = 1; o <= 2; o <<= 1) {
            float ov = __shfl_xor_sync(0xFFFFFFFFu, v, o);
            int oi = __shfl_xor_sync(0xFFFFFFFFu, i, o);
            if (ov > v || (ov == v && oi < i)) { v = ov; i = oi; }
        }
        if ((l & 3) == 0) {
            const int mi = slot >> 1, h = slot & 1;
            const int row = wm * 32 + mi * 16 + h * 8 + (l >> 2);
            mbest[wn * 128 + row] = v;
            midx[wn * 128 + row] = i;
        }
    }
    __syncthreads();
    if (t < 128) {
        float v0 = mbest[t], v1 = mbest[128 + t];
        int i0 = midx[t], i1 = midx[128 + t];
        bool p = (v1 > v0) || (v1 == v0 && i1 < i0);
        g_bidx[blk * 128 + t] = p ? i1 : i0;
    }
}

// ---------------- gather + qloss + EMA scatter ----------------
__global__ __launch_bounds__(256) void gather_kernel(const float* __restrict__ emb, float* __restrict__ out) {
    const int t = threadIdx.x;
    const int n = blockIdx.x * 256 + t;
    const int idx = g_bidx[n];
    const int b = n >> 12, p = n & (HWW - 1);

    float ev[EE];
    const float4* er = reinterpret_cast<const float4*>(emb + (size_t)idx * EE);
    #pragma unroll
    for (int i = 0; i < 8; i++) {
        float4 v = er[i];
        ev[4 * i] = v.x; ev[4 * i + 1] = v.y; ev[4 * i + 2] = v.z; ev[4 * i + 3] = v.w;
    }

    const float* zrow = g_z + (size_t)n * EE;
    float* dwr = g_dw + (size_t)idx * EE;
    float sq = 0.0f;
    #pragma unroll
    for (int e = 0; e < EE; e++) {
        float zv = zrow[e];
        float d = ev[e] - zv;
        sq = fmaf(d, d, sq);
        atomicAdd(&dwr[e], zv);
    }
    atomicAdd(&g_counts[idx], 1.0f);

    float* ob = out + OFF_ZQ + (size_t)b * EE * HWW + p;
    #pragma unroll
    for (int e = 0; e < EE; e++) ob[(size_t)e * HWW] = ev[e];

    out[OFF_IDX + n] = (float)idx;

    __shared__ float red[256];
    red[t] = sq;
    __syncthreads();
    #pragma unroll
    for (int s = 128; s; s >>= 1) {
        if (t < s) red[t] += red[t + s];
        __syncthreads();
    }
    if (t == 0) atomicAdd(&g_qsum, red[0]);
}

__global__ __launch_bounds__(256) void ema1_kernel(const float* __restrict__ ema_cs, float* __restrict__ out) {
    const int t = threadIdx.x;
    const int k = blockIdx.x * 256 + t;
    float c = DECAY * ema_cs[k] + ONE_MINUS_DECAY * g_counts[k];
    out[OFF_CS + k] = c;
    __shared__ float red[256];
    red[t] = c;
    __syncthreads();
    #pragma unroll
    for (int s = 128; s; s >>= 1) {
        if (t < s) red[t] += red[t + s];
        __syncthreads();
    }
    if (t == 0) atomicAdd(&g_nsum, red[0]);
}

__global__ __launch_bounds__(256) void ema2_kernel(const float* __restrict__ ema_w, float* __restrict__ out) {
    const int i = blockIdx.x * 256 + threadIdx.x;
    const int k = i >> 5;
    float w = DECAY * ema_w[i] + ONE_MINUS_DECAY * g_dw[i];
    out[OFF_W + i] = w;
    float nt = g_nsum;
    float c = out[OFF_CS + k];
    float cs = (c + EPSI) / (nt + (float)KK * EPSI) * nt;
    out[OFF_EMB + i] = w / cs;
    if (i == 0) out[OFF_QL] = BETA * g_qsum / (float)(NN * EE);
}

extern "C" void kernel_launch(void* const* d_in, const int* in_sizes, int n_in,
                              void* d_out, int out_size) {
    const float* x   = (const float*)d_in[0];
    const float* Wq  = (const float*)d_in[1];
    const float* bq  = (const float*)d_in[2];
    const float* emb = (const float*)d_in[3];
    const float* ecs = (const float*)d_in[4];
    const float* ew  = (const float*)d_in[5];
    float* out = (float*)d_out;

    cudaFuncSetAttribute(argmax_hmma_kernel, cudaFuncAttributeMaxDynamicSharedMemorySize, SMEM_TOTAL);

    zero_kernel<<<264, 512>>>();
    proj_kernel<<<NN / 16, 256>>>(x, Wq, bq);
    inorm_kernel<<<KK / 8, 256>>>(emb);
    pack_bh_kernel<<<KK / 16, 256>>>(emb);
    argmax_hmma_kernel<<<256, 256, SMEM_TOTAL>>>();
    gather_kernel<<<NN / 256, 256>>>(emb, out);
    ema1_kernel<<<KK / 256, 256>>>(ecs, out);
    ema2_kernel<<<(KK * EE) / 256, 256>>>(ew, out);
}

// round 16
// speedup vs baseline: 1.0446x; 1.0446x over previous
#include <cuda_runtime.h>
#include <cuda_fp16.h>
#include <cstdint>
#include <cfloat>

#define CC 256
#define EE 32
#define KK 8192
#define NN 32768
#define HWW 4096
#define NT2 128          // tiles of 64 codes

#define DECAY 0.99f
#define ONE_MINUS_DECAY 0.01f
#define EPSI 1e-5f
#define BETA 0.25f

#define OFF_ZQ   0
#define OFF_IDX  1048576
#define OFF_QL   1081344
#define OFF_EMB  1081345
#define OFF_CS   1343489
#define OFF_W    1351681

// Scratch (device globals)
__device__ float g_z[NN * EE];                    // fp32 z_flat
__device__ __align__(16) __half g_bh[KK * 128];   // 2MB: per code row, 128 f16 = [eh|eh|el|el]
__device__ float g_inorm[KK];
__device__ float g_counts[KK];
__device__ float g_dw[KK * EE];
__device__ int   g_bidx[NN];
__device__ float g_qsum;
__device__ float g_nsum;

// ---------------- helpers ----------------
__device__ __forceinline__ uint32_t smem_u32(const void* p) {
    uint32_t a;
    asm("{ .reg .u64 t; cvta.to.shared.u64 t, %1; cvt.u32.u64 %0, t; }" : "=r"(a) : "l"(p));
    return a;
}
__device__ __forceinline__ void cp_async16(uint32_t saddr, const void* gaddr) {
    asm volatile("cp.async.cg.shared.global [%0], [%1], 16;" :: "r"(saddr), "l"(gaddr) : "memory");
}
__device__ __forceinline__ void mma16816(float* c, const uint32_t* a, const uint32_t* b) {
    asm volatile("mma.sync.aligned.m16n8k16.row.col.f32.f16.f16.f32 "
        "{%0,%1,%2,%3}, {%4,%5,%6,%7}, {%8,%9}, {%0,%1,%2,%3};"
        : "+f"(c[0]), "+f"(c[1]), "+f"(c[2]), "+f"(c[3])
        : "r"(a[0]), "r"(a[1]), "r"(a[2]), "r"(a[3]), "r"(b[0]), "r"(b[1]));
}
__device__ __forceinline__ void ldsm4(uint32_t* r, uint32_t addr) {
    asm volatile("ldmatrix.sync.aligned.m8n8.x4.shared.b16 {%0,%1,%2,%3}, [%4];"
        : "=r"(r[0]), "=r"(r[1]), "=r"(r[2]), "=r"(r[3]) : "r"(addr));
}
__device__ __forceinline__ void ldsm2(uint32_t* r, uint32_t addr) {
    asm volatile("ldmatrix.sync.aligned.m8n8.x2.shared.b16 {%0,%1}, [%2];"
        : "=r"(r[0]), "=r"(r[1]) : "r"(addr));
}
// XOR swizzle: rows of 256B, permute 16B chunks within each 128B half by row&7
__device__ __forceinline__ int swz(int row, int byte_) {
    int c8 = byte_ >> 4;
    int c8s = (c8 & 8) | ((c8 ^ row) & 7);
    return row * 256 + (c8s << 4) + (byte_ & 15);
}

// ---------------- zero ----------------
__global__ void zero_kernel() {
    int i = blockIdx.x * blockDim.x + threadIdx.x;
    int stride = gridDim.x * blockDim.x;
    for (int j = i; j < KK * EE; j += stride) g_dw[j] = 0.0f;
    for (int j = i; j < KK; j += stride) g_counts[j] = 0.0f;
    if (i == 0) { g_qsum = 0.0f; g_nsum = 0.0f; }
}

// ---------------- 1x1 conv ----------------
__global__ __launch_bounds__(256) void proj_kernel(
    const float* __restrict__ x, const float* __restrict__ Wq, const float* __restrict__ bq)
{
    __shared__ float sW[EE * CC];
    __shared__ float sx[CC * 16];
    const int t = threadIdx.x;
    const int n0 = blockIdx.x * 16;
    const int b = n0 >> 12;
    const int p0 = n0 & (HWW - 1);

    for (int i = t; i < EE * CC; i += 256) sW[i] = Wq[i];
    const float* xb = x + (size_t)b * CC * HWW + p0;
    #pragma unroll
    for (int j = 0; j < 16; j++) {
        int idx = j * 256 + t;
        int c = idx >> 4, pix = idx & 15;
        sx[idx] = xb[c * HWW + pix];
    }
    __syncthreads();

    const int pix = t & 15;
    const int e0 = (t >> 4) << 1;
    float a0 = 0.0f, a1 = 0.0f;
    #pragma unroll 8
    for (int c = 0; c < CC; c++) {
        float xv = sx[c * 16 + pix];
        a0 = fmaf(xv, sW[(e0 + 0) * CC + c], a0);
        a1 = fmaf(xv, sW[(e0 + 1) * CC + c], a1);
    }
    float* zr = g_z + (size_t)(n0 + pix) * EE + e0;
    zr[0] = a0 + bq[e0];
    zr[1] = a1 + bq[e0 + 1];
}

// ---------------- embedding inverse norms (scaled by 256) ----------------
__global__ __launch_bounds__(256) void inorm_kernel(const float* __restrict__ emb) {
    int k = blockIdx.x * 8 + (threadIdx.x >> 5);
    int e = threadIdx.x & 31;
    float v = emb[k * EE + e];
    float s = v * v;
    #pragma unroll
    for (int o = 16; o; o >>= 1) s += __shfl_xor_sync(0xFFFFFFFFu, s, o);
    if (e == 0) g_inorm[k] = 256.0f / fmaxf(sqrtf(s), 1e-12f);
}

// ---------------- pack B: natural row-major [code][128] = [eh|eh|el|el] ----------------
__global__ __launch_bounds__(256) void pack_bh_kernel(const float* __restrict__ emb) {
    const int code = blockIdx.x * 16 + (threadIdx.x >> 4);
    const int e0 = (threadIdx.x & 15) * 2;
    const float inv = g_inorm[code];
    float v0 = emb[(size_t)code * EE + e0] * inv;
    float v1 = emb[(size_t)code * EE + e0 + 1] * inv;
    __half h0 = __float2half_rn(v0), h1 = __float2half_rn(v1);
    __half l0 = __float2half_rn(v0 - __half2float(h0));
    __half l1 = __float2half_rn(v1 - __half2float(h1));
    __half2 hh = __halves2half2(h0, h1);
    __half2 ll = __halves2half2(l0, l1);
    __half2* row = (__half2*)(g_bh + (size_t)code * 128);
    const int i2 = e0 >> 1;
    row[i2]      = hh;   // k in [0,32)
    row[i2 + 16] = hh;   // k in [32,64)
    row[i2 + 32] = ll;   // k in [64,96)
    row[i2 + 48] = ll;   // k in [96,128)
}

// ---------------- HMMA argmax: A-in-regs, register argmax + cross-warp merge,
//                  triple-buffered B -> ONE syncthreads per tile ----------------
// 256 CTAs x 256 thr (8 warps, 4m x 2n). M=128 pixels/CTA, 128 tiles of 64 codes, K=128.
// SMEM: A build 32KB @0 (reused: merge buffer), B triple buffer 3x16KB @32768. 80KB total.
#define SM_B_OFF 32768
#define SMEM_TOTAL (SM_B_OFF + 3 * 16384)

__global__ __launch_bounds__(256, 2) void argmax_hmma_kernel() {
    extern __shared__ __align__(16) char smem[];
    char* smA = smem;
    const int t = threadIdx.x;
    const int l = t & 31, wid = t >> 5;
    const int wm = wid & 3, wn = wid >> 2;
    const int blk = blockIdx.x;
    const uint32_t sbA = smem_u32(smA);
    const uint32_t sbB = sbA + SM_B_OFF;

    // ---- build A tile in smem: pixel rows, K=128 = [zh|zl|zh|zl], swizzled ----
    {
        const int row = t >> 1;
        const int e0 = (t & 1) * 16;
        const float4* zr = (const float4*)(g_z + (size_t)(blk * 128 + row) * EE + e0);
        float zf[16];
        #pragma unroll
        for (int i = 0; i < 4; i++) {
            float4 v = zr[i];
            zf[4 * i] = v.x; zf[4 * i + 1] = v.y; zf[4 * i + 2] = v.z; zf[4 * i + 3] = v.w;
        }
        #pragma unroll
        for (int i = 0; i < 16; i += 2) {
            float v0 = 256.0f * zf[i];
            float v1 = 256.0f * zf[i + 1];
            __half h0 = __float2half_rn(v0), h1 = __float2half_rn(v1);
            __half l0 = __float2half_rn(v0 - __half2float(h0));
            __half l1 = __float2half_rn(v1 - __half2float(h1));
            __half2 hh = __halves2half2(h0, h1);
            __half2 ll = __halves2half2(l0, l1);
            const int b0 = 2 * (e0 + i);
            *(__half2*)(smA + swz(row, b0))       = hh;   // k = e
            *(__half2*)(smA + swz(row, b0 + 64))  = ll;   // k = e+32
            *(__half2*)(smA + swz(row, b0 + 128)) = hh;   // k = e+64
            *(__half2*)(smA + swz(row, b0 + 192)) = ll;   // k = e+96
        }
    }

    // ---- prologue: async-load B tiles 0 and 1 (separate groups) ----
    #pragma unroll
    for (int pt = 0; pt < 2; pt++) {
        const uint4* src = (const uint4*)(g_bh + (size_t)pt * 64 * 128);
        uint32_t dst = sbB + pt * 16384;
        #pragma unroll
        for (int i = 0; i < 4; i++) {
            int c = t + i * 256;
            int row = c >> 4, c8 = c & 15;
            int c8s = (c8 & 8) | ((c8 ^ row) & 7);
            cp_async16(dst + row * 256 + (c8s << 4), src + c);
        }
        asm volatile("cp.async.commit_group;" ::: "memory");
    }

    __syncthreads();   // A build complete

    // ---- load A fragments into registers (once) ----
    const int arow0 = wm * 32 + (l & 15);
    const int abyte_lane = ((l >> 4) & 1) * 16;
    uint32_t afrag[8][8];   // [k-step][a0:0..3, a1:4..7]
    #pragma unroll
    for (int s = 0; s < 8; s++) {
        const int abyte = s * 32 + abyte_lane;
        ldsm4(&afrag[s][0], sbA + swz(arow0, abyte));
        ldsm4(&afrag[s][4], sbA + swz(arow0 + 16, abyte));
    }

    // per-thread running argmax over this warp's half-columns
    float best[4] = {-FLT_MAX, -FLT_MAX, -FLT_MAX, -FLT_MAX};
    int bidx[4] = {0, 0, 0, 0};

    const int brow_lane = (l & 7);
    const int bbyte_lane = ((l >> 3) & 1) * 16;

    // buffer index tracking: tile tt lives in buffer tt % 3
    int buf = 0, pbuf = 2;   // pbuf = (tt+2)%3 target
    for (int tt = 0; tt < NT2; tt++) {
        asm volatile("cp.async.wait_group 1;" ::: "memory");   // B(tt) complete (tt+1 in flight)
        __syncthreads();   // B(tt) visible; ALL warps done with tile tt-1 (buffer pbuf)

        // prefetch tile tt+2 into buffer (tt+2)%3 == buffer of tile tt-1, now free
        if (tt + 2 < NT2) {
            const uint4* src = (const uint4*)(g_bh + (size_t)(tt + 2) * 64 * 128);
            uint32_t dst = sbB + pbuf * 16384;
            #pragma unroll
            for (int i = 0; i < 4; i++) {
                int c = t + i * 256;
                int row = c >> 4, c8 = c & 15;
                int c8s = (c8 & 8) | ((c8 ^ row) & 7);
                cp_async16(dst + row * 256 + (c8s << 4), src + c);
            }
        }
        asm volatile("cp.async.commit_group;" ::: "memory");

        const uint32_t sB = sbB + buf * 16384;

        // ---- compute 128x64 scores ----
        float c_[2][4][4];
        #pragma unroll
        for (int mi = 0; mi < 2; mi++)
            #pragma unroll
            for (int j = 0; j < 4; j++)
                #pragma unroll
                for (int q = 0; q < 4; q++) c_[mi][j][q] = 0.0f;

        #pragma unroll
        for (int s = 0; s < 8; s++) {
            #pragma unroll
            for (int j = 0; j < 4; j++) {
                uint32_t b[2];
                const int brow = (wn * 4 + j) * 8 + brow_lane;
                ldsm2(b, sB + swz(brow, s * 32 + bbyte_lane));
                mma16816(c_[0][j], &afrag[s][0], b);
                mma16816(c_[1][j], &afrag[s][4], b);
            }
        }

        // ---- register argmax (ascending column order, strict >, explicit indices) ----
        const int colbase = tt * 64 + wn * 32 + (l & 3) * 2;
        #pragma unroll
        for (int mi = 0; mi < 2; mi++) {
            const int s0 = mi * 2;
            #pragma unroll
            for (int j = 0; j < 4; j++) {
                const int c0 = colbase + j * 8;
                if (c_[mi][j][0] > best[s0])     { best[s0] = c_[mi][j][0];     bidx[s0] = c0; }
                if (c_[mi][j][1] > best[s0])     { best[s0] = c_[mi][j][1];     bidx[s0] = c0 + 1; }
                if (c_[mi][j][2] > best[s0 + 1]) { best[s0 + 1] = c_[mi][j][2]; bidx[s0 + 1] = c0; }
                if (c_[mi][j][3] > best[s0 + 1]) { best[s0 + 1] = c_[mi][j][3]; bidx[s0 + 1] = c0 + 1; }
            }
        }

        buf = (buf == 2) ? 0 : buf + 1;
        pbuf = (pbuf == 2) ? 0 : pbuf + 1;
    }

    // ---- quad reduce within warp, then cross-wn merge via smem (the R14 fix) ----
    // smA is only read in the prologue; in-loop warps touch only sbB. Safe to reuse.
    float* mbest = (float*)smA;              // [2][128]
    int*   midx  = (int*)(smA + 1024);       // [2][128]
    #pragma unroll
    for (int slot = 0; slot < 4; slot++) {
        float v = best[slot];
        int i = bidx[slot];
        #pragma unroll
        for (int o = 1; o <= 2; o <<= 1) {
            float ov = __shfl_xor_sync(0xFFFFFFFFu, v, o);
            int oi = __shfl_xor_sync(0xFFFFFFFFu, i, o);
            if (ov > v || (ov == v && oi < i)) { v = ov; i = oi; }
        }
        if ((l & 3) == 0) {
            const int mi = slot >> 1, h = slot & 1;
            const int row = wm * 32 + mi * 16 + h * 8 + (l >> 2);
            mbest[wn * 128 + row] = v;
            midx[wn * 128 + row] = i;
        }
    }
    __syncthreads();
    if (t < 128) {
        float v0 = mbest[t], v1 = mbest[128 + t];
        int i0 = midx[t], i1 = midx[128 + t];
        bool p = (v1 > v0) || (v1 == v0 && i1 < i0);   // global first-max tie-break
        g_bidx[blk * 128 + t] = p ? i1 : i0;
    }
}

// ---------------- gather + qloss + EMA scatter ----------------
__global__ __launch_bounds__(256) void gather_kernel(const float* __restrict__ emb, float* __restrict__ out) {
    const int t = threadIdx.x;
    const int n = blockIdx.x * 256 + t;
    const int idx = g_bidx[n];
    const int b = n >> 12, p = n & (HWW - 1);

    float ev[EE];
    const float4* er = reinterpret_cast<const float4*>(emb + (size_t)idx * EE);
    #pragma unroll
    for (int i = 0; i < 8; i++) {
        float4 v = er[i];
        ev[4 * i] = v.x; ev[4 * i + 1] = v.y; ev[4 * i + 2] = v.z; ev[4 * i + 3] = v.w;
    }

    const float* zrow = g_z + (size_t)n * EE;
    float* dwr = g_dw + (size_t)idx * EE;
    float sq = 0.0f;
    #pragma unroll
    for (int e = 0; e < EE; e++) {
        float zv = zrow[e];
        float d = ev[e] - zv;
        sq = fmaf(d, d, sq);
        atomicAdd(&dwr[e], zv);
    }
    atomicAdd(&g_counts[idx], 1.0f);

    float* ob = out + OFF_ZQ + (size_t)b * EE * HWW + p;
    #pragma unroll
    for (int e = 0; e < EE; e++) ob[(size_t)e * HWW] = ev[e];

    out[OFF_IDX + n] = (float)idx;

    __shared__ float red[256];
    red[t] = sq;
    __syncthreads();
    #pragma unroll
    for (int s = 128; s; s >>= 1) {
        if (t < s) red[t] += red[t + s];
        __syncthreads();
    }
    if (t == 0) atomicAdd(&g_qsum, red[0]);
}

__global__ __launch_bounds__(256) void ema1_kernel(const float* __restrict__ ema_cs, float* __restrict__ out) {
    const int t = threadIdx.x;
    const int k = blockIdx.x * 256 + t;
    float c = DECAY * ema_cs[k] + ONE_MINUS_DECAY * g_counts[k];
    out[OFF_CS + k] = c;
    __shared__ float red[256];
    red[t] = c;
    __syncthreads();
    #pragma unroll
    for (int s = 128; s; s >>= 1) {
        if (t < s) red[t] += red[t + s];
        __syncthreads();
    }
    if (t == 0) atomicAdd(&g_nsum, red[0]);
}

__global__ __launch_bounds__(256) void ema2_kernel(const float* __restrict__ ema_w, float* __restrict__ out) {
    const int i = blockIdx.x * 256 + threadIdx.x;
    const int k = i >> 5;
    float w = DECAY * ema_w[i] + ONE_MINUS_DECAY * g_dw[i];
    out[OFF_W + i] = w;
    float nt = g_nsum;
    float c = out[OFF_CS + k];
    float cs = (c + EPSI) / (nt + (float)KK * EPSI) * nt;
    out[OFF_EMB + i] = w / cs;
    if (i == 0) out[OFF_QL] = BETA * g_qsum / (float)(NN * EE);
}

extern "C" void kernel_launch(void* const* d_in, const int* in_sizes, int n_in,
                              void* d_out, int out_size) {
    const float* x   = (const float*)d_in[0];
    const float* Wq  = (const float*)d_in[1];
    const float* bq  = (const float*)d_in[2];
    const float* emb = (const float*)d_in[3];
    const float* ecs = (const float*)d_in[4];
    const float* ew  = (const float*)d_in[5];
    float* out = (float*)d_out;

    cudaFuncSetAttribute(argmax_hmma_kernel, cudaFuncAttributeMaxDynamicSharedMemorySize, SMEM_TOTAL);

    zero_kernel<<<264, 512>>>();
    proj_kernel<<<NN / 16, 256>>>(x, Wq, bq);
    inorm_kernel<<<KK / 8, 256>>>(emb);
    pack_bh_kernel<<<KK / 16, 256>>>(emb);
    argmax_hmma_kernel<<<256, 256, SMEM_TOTAL>>>();
    gather_kernel<<<NN / 256, 256>>>(emb, out);
    ema1_kernel<<<KK / 256, 256>>>(ecs, out);
    ema2_kernel<<<(KK * EE) / 256, 256>>>(ew, out);
}

// round 17
// speedup vs baseline: 1.0633x; 1.0179x over previous
#include <cuda_runtime.h>
#include <cuda_fp16.h>
#include <cstdint>
#include <cfloat>

#define CC 256
#define EE 32
#define KK 8192
#define NN 32768
#define HWW 4096
#define NT2 128          // tiles of 64 codes

#define DECAY 0.99f
#define ONE_MINUS_DECAY 0.01f
#define EPSI 1e-5f
#define BETA 0.25f

#define OFF_ZQ   0
#define OFF_IDX  1048576
#define OFF_QL   1081344
#define OFF_EMB  1081345
#define OFF_CS   1343489
#define OFF_W    1351681

// Scratch (device globals)
__device__ float g_z[NN * EE];                    // fp32 z_flat
__device__ __align__(16) __half g_bh[KK * 128];   // 2MB: per code row, 128 f16 = [eh|eh|el|el]
__device__ float g_counts[KK];
__device__ float g_dw[KK * EE];
__device__ float g_qsum;
__device__ float g_nsum;

// ---------------- helpers ----------------
__device__ __forceinline__ uint32_t smem_u32(const void* p) {
    uint32_t a;
    asm("{ .reg .u64 t; cvta.to.shared.u64 t, %1; cvt.u32.u64 %0, t; }" : "=r"(a) : "l"(p));
    return a;
}
__device__ __forceinline__ void cp_async16(uint32_t saddr, const void* gaddr) {
    asm volatile("cp.async.cg.shared.global [%0], [%1], 16;" :: "r"(saddr), "l"(gaddr) : "memory");
}
__device__ __forceinline__ void mma16816(float* c, const uint32_t* a, const uint32_t* b) {
    asm volatile("mma.sync.aligned.m16n8k16.row.col.f32.f16.f16.f32 "
        "{%0,%1,%2,%3}, {%4,%5,%6,%7}, {%8,%9}, {%0,%1,%2,%3};"
        : "+f"(c[0]), "+f"(c[1]), "+f"(c[2]), "+f"(c[3])
        : "r"(a[0]), "r"(a[1]), "r"(a[2]), "r"(a[3]), "r"(b[0]), "r"(b[1]));
}
__device__ __forceinline__ void ldsm4(uint32_t* r, uint32_t addr) {
    asm volatile("ldmatrix.sync.aligned.m8n8.x4.shared.b16 {%0,%1,%2,%3}, [%4];"
        : "=r"(r[0]), "=r"(r[1]), "=r"(r[2]), "=r"(r[3]) : "r"(addr));
}
__device__ __forceinline__ void ldsm2(uint32_t* r, uint32_t addr) {
    asm volatile("ldmatrix.sync.aligned.m8n8.x2.shared.b16 {%0,%1}, [%2];"
        : "=r"(r[0]), "=r"(r[1]) : "r"(addr));
}
// XOR swizzle: rows of 256B, permute 16B chunks within each 128B half by row&7
__device__ __forceinline__ int swz(int row, int byte_) {
    int c8 = byte_ >> 4;
    int c8s = (c8 & 8) | ((c8 ^ row) & 7);
    return row * 256 + (c8s << 4) + (byte_ & 15);
}

// ---------------- zero ----------------
__global__ void zero_kernel() {
    int i = blockIdx.x * blockDim.x + threadIdx.x;
    int stride = gridDim.x * blockDim.x;
    for (int j = i; j < KK * EE; j += stride) g_dw[j] = 0.0f;
    for (int j = i; j < KK; j += stride) g_counts[j] = 0.0f;
    if (i == 0) { g_qsum = 0.0f; g_nsum = 0.0f; }
}

// ---------------- fused: embedding inverse norm + pack B [eh|eh|el|el] ----------------
__global__ __launch_bounds__(256) void inormpack_kernel(const float* __restrict__ emb) {
    const int k = blockIdx.x * 8 + (threadIdx.x >> 5);
    const int e = threadIdx.x & 31;
    float v = emb[(size_t)k * EE + e];
    float s = v * v;
    #pragma unroll
    for (int o = 16; o; o >>= 1) s += __shfl_xor_sync(0xFFFFFFFFu, s, o);
    const float vs = v * (256.0f / fmaxf(sqrtf(s), 1e-12f));
    __half hh = __float2half_rn(vs);
    __half ll = __float2half_rn(vs - __half2float(hh));
    __half* row = g_bh + (size_t)k * 128;
    row[e] = hh;        // k in [0,32)
    row[32 + e] = hh;   // k in [32,64)
    row[64 + e] = ll;   // k in [64,96)
    row[96 + e] = ll;   // k in [96,128)
}

// ---------------- 1x1 conv ----------------
__global__ __launch_bounds__(256) void proj_kernel(
    const float* __restrict__ x, const float* __restrict__ Wq, const float* __restrict__ bq)
{
    __shared__ float sW[EE * CC];
    __shared__ float sx[CC * 16];
    const int t = threadIdx.x;
    const int n0 = blockIdx.x * 16;
    const int b = n0 >> 12;
    const int p0 = n0 & (HWW - 1);

    for (int i = t; i < EE * CC; i += 256) sW[i] = Wq[i];
    const float* xb = x + (size_t)b * CC * HWW + p0;
    #pragma unroll
    for (int j = 0; j < 16; j++) {
        int idx = j * 256 + t;
        int c = idx >> 4, pix = idx & 15;
        sx[idx] = xb[c * HWW + pix];
    }
    __syncthreads();

    const int pix = t & 15;
    const int e0 = (t >> 4) << 1;
    float a0 = 0.0f, a1 = 0.0f;
    #pragma unroll 8
    for (int c = 0; c < CC; c++) {
        float xv = sx[c * 16 + pix];
        a0 = fmaf(xv, sW[(e0 + 0) * CC + c], a0);
        a1 = fmaf(xv, sW[(e0 + 1) * CC + c], a1);
    }
    float* zr = g_z + (size_t)(n0 + pix) * EE + e0;
    zr[0] = a0 + bq[e0];
    zr[1] = a1 + bq[e0 + 1];
}

// ---------------- HMMA argmax + fused gather/qloss/EMA-scatter ----------------
// 256 CTAs x 256 thr (8 warps, 4m x 2n). M=128 pixels/CTA, 128 tiles of 64 codes, K=128.
// SMEM: A build 32KB @0 (reused: merge/fidx buffers), B triple buffer 3x16KB @32768. 80KB.
#define SM_B_OFF 32768
#define SMEM_TOTAL (SM_B_OFF + 3 * 16384)

__global__ __launch_bounds__(256, 2) void argmax_hmma_kernel(
    const float* __restrict__ emb, float* __restrict__ out)
{
    extern __shared__ __align__(16) char smem[];
    char* smA = smem;
    const int t = threadIdx.x;
    const int l = t & 31, wid = t >> 5;
    const int wm = wid & 3, wn = wid >> 2;
    const int blk = blockIdx.x;
    const uint32_t sbA = smem_u32(smA);
    const uint32_t sbB = sbA + SM_B_OFF;

    // ---- build A tile in smem: pixel rows, K=128 = [zh|zl|zh|zl], swizzled ----
    {
        const int row = t >> 1;
        const int e0 = (t & 1) * 16;
        const float4* zr = (const float4*)(g_z + (size_t)(blk * 128 + row) * EE + e0);
        float zf[16];
        #pragma unroll
        for (int i = 0; i < 4; i++) {
            float4 v = zr[i];
            zf[4 * i] = v.x; zf[4 * i + 1] = v.y; zf[4 * i + 2] = v.z; zf[4 * i + 3] = v.w;
        }
        #pragma unroll
        for (int i = 0; i < 16; i += 2) {
            float v0 = 256.0f * zf[i];
            float v1 = 256.0f * zf[i + 1];
            __half h0 = __float2half_rn(v0), h1 = __float2half_rn(v1);
            __half l0 = __float2half_rn(v0 - __half2float(h0));
            __half l1 = __float2half_rn(v1 - __half2float(h1));
            __half2 hh = __halves2half2(h0, h1);
            __half2 ll = __halves2half2(l0, l1);
            const int b0 = 2 * (e0 + i);
            *(__half2*)(smA + swz(row, b0))       = hh;   // k = e
            *(__half2*)(smA + swz(row, b0 + 64))  = ll;   // k = e+32
            *(__half2*)(smA + swz(row, b0 + 128)) = hh;   // k = e+64
            *(__half2*)(smA + swz(row, b0 + 192)) = ll;   // k = e+96
        }
    }

    // ---- prologue: async-load B tiles 0 and 1 (separate groups) ----
    #pragma unroll
    for (int pt = 0; pt < 2; pt++) {
        const uint4* src = (const uint4*)(g_bh + (size_t)pt * 64 * 128);
        uint32_t dst = sbB + pt * 16384;
        #pragma unroll
        for (int i = 0; i < 4; i++) {
            int c = t + i * 256;
            int row = c >> 4, c8 = c & 15;
            int c8s = (c8 & 8) | ((c8 ^ row) & 7);
            cp_async16(dst + row * 256 + (c8s << 4), src + c);
        }
        asm volatile("cp.async.commit_group;" ::: "memory");
    }

    __syncthreads();   // A build complete

    // ---- load A fragments into registers (once) ----
    const int arow0 = wm * 32 + (l & 15);
    const int abyte_lane = ((l >> 4) & 1) * 16;
    uint32_t afrag[8][8];   // [k-step][a0:0..3, a1:4..7]
    #pragma unroll
    for (int s = 0; s < 8; s++) {
        const int abyte = s * 32 + abyte_lane;
        ldsm4(&afrag[s][0], sbA + swz(arow0, abyte));
        ldsm4(&afrag[s][4], sbA + swz(arow0 + 16, abyte));
    }

    // per-thread running argmax over this warp's half-columns
    float best[4] = {-FLT_MAX, -FLT_MAX, -FLT_MAX, -FLT_MAX};
    int bidx[4] = {0, 0, 0, 0};

    const int brow_lane = (l & 7);
    const int bbyte_lane = ((l >> 3) & 1) * 16;

    // buffer index tracking: tile tt lives in buffer tt % 3
    int buf = 0, pbuf = 2;   // pbuf = (tt+2)%3 target
    for (int tt = 0; tt < NT2; tt++) {
        asm volatile("cp.async.wait_group 1;" ::: "memory");   // B(tt) complete (tt+1 in flight)
        __syncthreads();   // B(tt) visible; ALL warps done with tile tt-1 (buffer pbuf)

        // prefetch tile tt+2 into buffer of tile tt-1 (now free)
        if (tt + 2 < NT2) {
            const uint4* src = (const uint4*)(g_bh + (size_t)(tt + 2) * 64 * 128);
            uint32_t dst = sbB + pbuf * 16384;
            #pragma unroll
            for (int i = 0; i < 4; i++) {
                int c = t + i * 256;
                int row = c >> 4, c8 = c & 15;
                int c8s = (c8 & 8) | ((c8 ^ row) & 7);
                cp_async16(dst + row * 256 + (c8s << 4), src + c);
            }
        }
        asm volatile("cp.async.commit_group;" ::: "memory");

        const uint32_t sB = sbB + buf * 16384;

        // ---- compute 128x64 scores ----
        float c_[2][4][4];
        #pragma unroll
        for (int mi = 0; mi < 2; mi++)
            #pragma unroll
            for (int j = 0; j < 4; j++)
                #pragma unroll
                for (int q = 0; q < 4; q++) c_[mi][j][q] = 0.0f;

        #pragma unroll
        for (int s = 0; s < 8; s++) {
            #pragma unroll
            for (int j = 0; j < 4; j++) {
                uint32_t b[2];
                const int brow = (wn * 4 + j) * 8 + brow_lane;
                ldsm2(b, sB + swz(brow, s * 32 + bbyte_lane));
                mma16816(c_[0][j], &afrag[s][0], b);
                mma16816(c_[1][j], &afrag[s][4], b);
            }
        }

        // ---- register argmax (ascending column order, strict >, explicit indices) ----
        const int colbase = tt * 64 + wn * 32 + (l & 3) * 2;
        #pragma unroll
        for (int mi = 0; mi < 2; mi++) {
            const int s0 = mi * 2;
            #pragma unroll
            for (int j = 0; j < 4; j++) {
                const int c0 = colbase + j * 8;
                if (c_[mi][j][0] > best[s0])     { best[s0] = c_[mi][j][0];     bidx[s0] = c0; }
                if (c_[mi][j][1] > best[s0])     { best[s0] = c_[mi][j][1];     bidx[s0] = c0 + 1; }
                if (c_[mi][j][2] > best[s0 + 1]) { best[s0 + 1] = c_[mi][j][2]; bidx[s0 + 1] = c0; }
                if (c_[mi][j][3] > best[s0 + 1]) { best[s0 + 1] = c_[mi][j][3]; bidx[s0 + 1] = c0 + 1; }
            }
        }

        buf = (buf == 2) ? 0 : buf + 1;
        pbuf = (pbuf == 2) ? 0 : pbuf + 1;
    }

    // ---- quad reduce within warp, then cross-wn merge via smem (the R14 fix) ----
    float* mbest = (float*)smA;              // [2][128]
    int*   midx  = (int*)(smA + 1024);       // [2][128]
    int*   fidx  = (int*)(smA + 2048);       // [128] final indices
    #pragma unroll
    for (int slot = 0; slot < 4; slot++) {
        float v = best[slot];
        int i = bidx[slot];
        #pragma unroll
        for (int o = 1; o <= 2; o <<= 1) {
            float ov = __shfl_xor_sync(0xFFFFFFFFu, v, o);
            int oi = __shfl_xor_sync(0xFFFFFFFFu, i, o);
            if (ov > v || (ov == v && oi < i)) { v = ov; i = oi; }
        }
        if ((l & 3) == 0) {
            const int mi = slot >> 1, h = slot & 1;
            const int row = wm * 32 + mi * 16 + h * 8 + (l >> 2);
            mbest[wn * 128 + row] = v;
            midx[wn * 128 + row] = i;
        }
    }
    __syncthreads();
    if (t < 128) {
        float v0 = mbest[t], v1 = mbest[128 + t];
        int i0 = midx[t], i1 = midx[128 + t];
        bool p = (v1 > v0) || (v1 == v0 && i1 < i0);   // global first-max tie-break
        fidx[t] = p ? i1 : i0;
    }
    __syncthreads();

    // ---- fused gather + qloss + EMA scatter (2 threads per pixel) ----
    {
        const int row = t >> 1;
        const int e0 = (t & 1) * 16;
        const int n = blk * 128 + row;
        const int idx = fidx[row];
        const int b = n >> 12, p = n & (HWW - 1);

        float ev[16], zv[16];
        const float4* er = (const float4*)(emb + (size_t)idx * EE + e0);
        const float4* zr = (const float4*)(g_z + (size_t)n * EE + e0);
        #pragma unroll
        for (int i = 0; i < 4; i++) {
            float4 v = er[i];
            ev[4 * i] = v.x; ev[4 * i + 1] = v.y; ev[4 * i + 2] = v.z; ev[4 * i + 3] = v.w;
            float4 z = zr[i];
            zv[4 * i] = z.x; zv[4 * i + 1] = z.y; zv[4 * i + 2] = z.z; zv[4 * i + 3] = z.w;
        }

        float* dwr = g_dw + (size_t)idx * EE + e0;
        float sq = 0.0f;
        float* ob = out + OFF_ZQ + (size_t)b * EE * HWW + (size_t)e0 * HWW + p;
        #pragma unroll
        for (int e = 0; e < 16; e++) {
            float d = ev[e] - zv[e];
            sq = fmaf(d, d, sq);
            atomicAdd(&dwr[e], zv[e]);
            ob[(size_t)e * HWW] = ev[e];
        }
        if ((t & 1) == 0) {
            out[OFF_IDX + n] = (float)idx;
            atomicAdd(&g_counts[idx], 1.0f);
        }

        // block reduce sq -> g_qsum
        float* red = (float*)smA;   // reuse (post-sync)
        __syncthreads();
        red[t] = sq;
        __syncthreads();
        #pragma unroll
        for (int s = 128; s; s >>= 1) {
            if (t < s) red[t] += red[t + s];
            __syncthreads();
        }
        if (t == 0) atomicAdd(&g_qsum, red[0]);
    }
}

__global__ __launch_bounds__(256) void ema1_kernel(const float* __restrict__ ema_cs, float* __restrict__ out) {
    const int t = threadIdx.x;
    const int k = blockIdx.x * 256 + t;
    float c = DECAY * ema_cs[k] + ONE_MINUS_DECAY * g_counts[k];
    out[OFF_CS + k] = c;
    __shared__ float red[256];
    red[t] = c;
    __syncthreads();
    #pragma unroll
    for (int s = 128; s; s >>= 1) {
        if (t < s) red[t] += red[t + s];
        __syncthreads();
    }
    if (t == 0) atomicAdd(&g_nsum, red[0]);
}

__global__ __launch_bounds__(256) void ema2_kernel(const float* __restrict__ ema_w, float* __restrict__ out) {
    const int i = blockIdx.x * 256 + threadIdx.x;
    const int k = i >> 5;
    float w = DECAY * ema_w[i] + ONE_MINUS_DECAY * g_dw[i];
    out[OFF_W + i] = w;
    float nt = g_nsum;
    float c = out[OFF_CS + k];
    float cs = (c + EPSI) / (nt + (float)KK * EPSI) * nt;
    out[OFF_EMB + i] = w / cs;
    if (i == 0) out[OFF_QL] = BETA * g_qsum / (float)(NN * EE);
}

extern "C" void kernel_launch(void* const* d_in, const int* in_sizes, int n_in,
                              void* d_out, int out_size) {
    const float* x   = (const float*)d_in[0];
    const float* Wq  = (const float*)d_in[1];
    const float* bq  = (const float*)d_in[2];
    const float* emb = (const float*)d_in[3];
    const float* ecs = (const float*)d_in[4];
    const float* ew  = (const float*)d_in[5];
    float* out = (float*)d_out;

    cudaFuncSetAttribute(argmax_hmma_kernel, cudaFuncAttributeMaxDynamicSharedMemorySize, SMEM_TOTAL);

    zero_kernel<<<264, 512>>>();
    inormpack_kernel<<<KK / 8, 256>>>(emb);
    proj_kernel<<<NN / 16, 256>>>(x, Wq, bq);
    argmax_hmma_kernel<<<256, 256, SMEM_TOTAL>>>(emb, out);
    ema1_kernel<<<KK / 256, 256>>>(ecs, out);
    ema2_kernel<<<(KK * EE) / 256, 256>>>(ew, out);
}